// round 2
// baseline (speedup 1.0000x reference)
#include <cuda_runtime.h>
#include <cstdint>

// Problem dims
#define B_BATCH   128
#define T_SEQ     2048
#define K_DIM     128    // J (softmax / contraction dim)
#define N_DIM     512    // d (output feature dim)
#define M_TILE    128
#define NCHUNK    128    // N processed in 4 chunks of 128
#define NCHUNKS   4

#define A_STRIDE  132    // floats per A row (pad 4 -> conflict-free frag loads)
#define B_STRIDE  136    // floats per B row (pad 8 -> conflict-free frag loads)
#define A_BYTES   (128 * A_STRIDE * 4)          // 67,584
#define B_BYTES   (128 * B_STRIDE * 4)          // 69,632
static constexpr unsigned SMEM_TOTAL = A_BYTES + 2 * B_BYTES;  // 206,848 B

// ---------------- helpers ----------------
static __device__ __forceinline__ uint32_t smem_u32(const void* p) {
    uint32_t a;
    asm("{ .reg .u64 t; cvta.to.shared.u64 t, %1; cvt.u32.u64 %0, t; }" : "=r"(a) : "l"(p));
    return a;
}

static __device__ __forceinline__ uint32_t f32_to_tf32(float f) {
    uint32_t r;
    asm("cvt.rna.tf32.f32 %0, %1;" : "=r"(r) : "f"(f));
    return r;
}

static __device__ __forceinline__ void cp_async16(uint32_t saddr, const float* gptr) {
    asm volatile("cp.async.cg.shared.global [%0], [%1], 16;"
                 :: "r"(saddr), "l"(gptr) : "memory");
}
static __device__ __forceinline__ void cp_commit() {
    asm volatile("cp.async.commit_group;" ::: "memory");
}
template <int N>
static __device__ __forceinline__ void cp_wait() {
    asm volatile("cp.async.wait_group %0;" :: "n"(N) : "memory");
}

static __device__ __forceinline__ void mma_tf32(
    float& c0, float& c1, float& c2, float& c3,
    uint32_t a0, uint32_t a1, uint32_t a2, uint32_t a3,
    uint32_t b0, uint32_t b1)
{
    asm volatile(
        "mma.sync.aligned.m16n8k8.row.col.f32.tf32.tf32.f32 "
        "{%0,%1,%2,%3}, {%4,%5,%6,%7}, {%8,%9}, {%0,%1,%2,%3};"
        : "+f"(c0), "+f"(c1), "+f"(c2), "+f"(c3)
        : "r"(a0), "r"(a1), "r"(a2), "r"(a3), "r"(b0), "r"(b1));
}

// ---------------- kernel ----------------
// Grid: (T_SEQ/M_TILE=16, B_BATCH=128). 256 threads = 8 warps.
// Warp layout: warpM = wid&1 (2 x 64 rows), warpN = wid>>1 (4 x 32 cols per chunk).
__global__ void __launch_bounds__(256, 1)
C2Q_15032385536516_kernel(const float* __restrict__ U,
                          const float* __restrict__ S,
                          float* __restrict__ Out)
{
    extern __shared__ char smem[];
    uint32_t* As = reinterpret_cast<uint32_t*>(smem);      // [128][A_STRIDE] tf32 probs
    const uint32_t sbase = smem_u32(smem);

    const int tid  = threadIdx.x;
    const int lane = tid & 31;
    const int wid  = tid >> 5;
    const int b    = blockIdx.y;
    const int m0   = blockIdx.x * M_TILE;
    const float* __restrict__ Ub = U + (size_t)b * K_DIM * N_DIM;

    // ---- prologue: async-load B chunk 0 into buffer 0 ----
    {
        const uint32_t bb = sbase + A_BYTES;
#pragma unroll
        for (int it = 0; it < 16; ++it) {
            const int idx = it * 256 + tid;
            const int k   = idx >> 5;          // 0..127
            const int n4  = idx & 31;          // float4 index within row
            cp_async16(bb + (uint32_t)(k * B_STRIDE + n4 * 4) * 4u,
                       Ub + (size_t)k * N_DIM + n4 * 4);
        }
        cp_commit();
    }

    // ---- fused softmax: 2 threads per row, each owns 64 of 128 cols ----
    {
        const int row  = tid >> 1;
        const int half = tid & 1;
        const float4* sp = reinterpret_cast<const float4*>(
            S + (size_t)(b * T_SEQ + m0 + row) * K_DIM + half * 64);
        float4 e[16];
        float sum = 0.f;
#pragma unroll
        for (int i = 0; i < 16; ++i) {
            float4 x = sp[i];
            e[i].x = __expf(x.x); e[i].y = __expf(x.y);
            e[i].z = __expf(x.z); e[i].w = __expf(x.w);
            sum += (e[i].x + e[i].y) + (e[i].z + e[i].w);
        }
        sum += __shfl_xor_sync(0xffffffffu, sum, 1);
        const float inv = 1.0f / sum;
        uint32_t* arow = As + row * A_STRIDE + half * 64;
#pragma unroll
        for (int i = 0; i < 16; ++i) {
            arow[4 * i + 0] = f32_to_tf32(e[i].x * inv);
            arow[4 * i + 1] = f32_to_tf32(e[i].y * inv);
            arow[4 * i + 2] = f32_to_tf32(e[i].z * inv);
            arow[4 * i + 3] = f32_to_tf32(e[i].w * inv);
        }
    }

    // ---- per-thread fragment bases ----
    const int warpM = wid & 1;
    const int warpN = wid >> 1;
    const int aIdx0 = (warpM * 64 + (lane >> 2)) * A_STRIDE + (lane & 3);
    const int bIdx0 = (lane & 3) * B_STRIDE + warpN * 32 + (lane >> 2);
    float* outBase = Out + (size_t)(b * T_SEQ + m0) * N_DIM;

    // ---- main loop over 4 N-chunks, double-buffered B ----
#pragma unroll 1
    for (int c = 0; c < NCHUNKS; ++c) {
        __syncthreads();   // all warps done with MMA on buffer (c+1)&1 (chunk c-1)

        if (c + 1 < NCHUNKS) {
            const uint32_t bb = sbase + A_BYTES + (uint32_t)((c + 1) & 1) * B_BYTES;
            const int n0 = (c + 1) * NCHUNK;
#pragma unroll
            for (int it = 0; it < 16; ++it) {
                const int idx = it * 256 + tid;
                const int k   = idx >> 5;
                const int n4  = idx & 31;
                cp_async16(bb + (uint32_t)(k * B_STRIDE + n4 * 4) * 4u,
                           Ub + (size_t)k * N_DIM + n0 + n4 * 4);
            }
            cp_commit();
            cp_wait<1>();   // chunk c complete (one group pending)
        } else {
            cp_wait<0>();   // last chunk: everything complete
        }
        __syncthreads();    // chunk c data visible to all warps

        const uint32_t* Bp = reinterpret_cast<const uint32_t*>(
            smem + A_BYTES + (size_t)(c & 1) * B_BYTES);

        float acc[4][4][4];
#pragma unroll
        for (int mf = 0; mf < 4; ++mf)
#pragma unroll
            for (int nf = 0; nf < 4; ++nf)
#pragma unroll
                for (int r = 0; r < 4; ++r) acc[mf][nf][r] = 0.f;

#pragma unroll 4
        for (int s = 0; s < 16; ++s) {
            uint32_t a[4][4];
#pragma unroll
            for (int mf = 0; mf < 4; ++mf) {
                const int base = aIdx0 + mf * 16 * A_STRIDE + s * 8;
                a[mf][0] = As[base];
                a[mf][1] = As[base + 8 * A_STRIDE];
                a[mf][2] = As[base + 4];
                a[mf][3] = As[base + 8 * A_STRIDE + 4];
            }
            uint32_t bfr[4][2];
#pragma unroll
            for (int nf = 0; nf < 4; ++nf) {
                const int base = bIdx0 + s * 8 * B_STRIDE + nf * 8;
                bfr[nf][0] = Bp[base];
                bfr[nf][1] = Bp[base + 4 * B_STRIDE];
            }
#pragma unroll
            for (int mf = 0; mf < 4; ++mf)
#pragma unroll
                for (int nf = 0; nf < 4; ++nf)
                    mma_tf32(acc[mf][nf][0], acc[mf][nf][1],
                             acc[mf][nf][2], acc[mf][nf][3],
                             a[mf][0], a[mf][1], a[mf][2], a[mf][3],
                             bfr[nf][0], bfr[nf][1]);
        }

        // ---- epilogue: stream accumulators to GMEM ----
        const int colBase = c * NCHUNK + warpN * 32 + 2 * (lane & 3);
        const int rowBase = warpM * 64 + (lane >> 2);
#pragma unroll
        for (int mf = 0; mf < 4; ++mf) {
            const int r0 = rowBase + mf * 16;
#pragma unroll
            for (int nf = 0; nf < 4; ++nf) {
                const int col = colBase + nf * 8;
                float2 v0 = make_float2(acc[mf][nf][0], acc[mf][nf][1]);
                float2 v1 = make_float2(acc[mf][nf][2], acc[mf][nf][3]);
                __stcs(reinterpret_cast<float2*>(outBase + (size_t)r0 * N_DIM + col), v0);
                __stcs(reinterpret_cast<float2*>(outBase + (size_t)(r0 + 8) * N_DIM + col), v1);
            }
        }
    }
}

extern "C" void kernel_launch(void* const* d_in, const int* in_sizes, int n_in,
                              void* d_out, int out_size)
{
    const float* U = (const float*)d_in[0];
    const float* S = (const float*)d_in[1];
    // Robustness: U has 8.4M elements, S has 33.5M. Swap if order differs.
    if (n_in >= 2 && in_sizes[0] == B_BATCH * T_SEQ * K_DIM) {
        const float* t = U; U = S; S = t;
    }
    float* Out = (float*)d_out;

    static int attr_set = 0;
    if (!attr_set) {
        cudaFuncSetAttribute(C2Q_15032385536516_kernel,
                             cudaFuncAttributeMaxDynamicSharedMemorySize, SMEM_TOTAL);
        attr_set = 1;
    }
    dim3 grid(T_SEQ / M_TILE, B_BATCH, 1);  // (16, 128)
    C2Q_15032385536516_kernel<<<grid, 256, SMEM_TOTAL>>>(U, S, Out);
}

// round 3
// speedup vs baseline: 1.0169x; 1.0169x over previous
#include <cuda_runtime.h>
#include <cstdint>

// Problem dims
#define B_BATCH   128
#define T_SEQ     2048
#define K_DIM     128    // J (softmax / contraction dim)
#define N_DIM     512    // d (output feature dim)
#define M_TILE    128
#define NCHUNK    128    // N processed in 4 chunks of 128
#define NCHUNKS   4

#define A_STRIDE  132    // floats per A row (pad 4 -> conflict-free ldsm/frag loads)
#define B_STRIDE  136    // floats per B row (pad 8 -> conflict-free frag loads)
#define A_BYTES   (128 * A_STRIDE * 4)          // 67,584
#define B_BYTES   (128 * B_STRIDE * 4)          // 69,632
static constexpr unsigned SMEM_TOTAL = A_BYTES + 2 * B_BYTES;  // 206,848 B

// ---------------- helpers ----------------
static __device__ __forceinline__ uint32_t smem_u32(const void* p) {
    uint32_t a;
    asm("{ .reg .u64 t; cvta.to.shared.u64 t, %1; cvt.u32.u64 %0, t; }" : "=r"(a) : "l"(p));
    return a;
}

static __device__ __forceinline__ uint32_t f32_to_tf32(float f) {
    uint32_t r;
    asm("cvt.rna.tf32.f32 %0, %1;" : "=r"(r) : "f"(f));
    return r;
}

static __device__ __forceinline__ void cp_async16(uint32_t saddr, const float* gptr) {
    asm volatile("cp.async.cg.shared.global [%0], [%1], 16;"
                 :: "r"(saddr), "l"(gptr) : "memory");
}
static __device__ __forceinline__ void cp_commit() {
    asm volatile("cp.async.commit_group;" ::: "memory");
}
template <int N>
static __device__ __forceinline__ void cp_wait() {
    asm volatile("cp.async.wait_group %0;" :: "n"(N) : "memory");
}

static __device__ __forceinline__ void ldsm_x4(
    uint32_t& r0, uint32_t& r1, uint32_t& r2, uint32_t& r3, uint32_t addr)
{
    asm volatile("ldmatrix.sync.aligned.m8n8.x4.shared.b16 {%0,%1,%2,%3}, [%4];"
                 : "=r"(r0), "=r"(r1), "=r"(r2), "=r"(r3) : "r"(addr));
}

static __device__ __forceinline__ void mma_tf32(
    float& c0, float& c1, float& c2, float& c3,
    uint32_t a0, uint32_t a1, uint32_t a2, uint32_t a3,
    uint32_t b0, uint32_t b1)
{
    asm volatile(
        "mma.sync.aligned.m16n8k8.row.col.f32.tf32.tf32.f32 "
        "{%0,%1,%2,%3}, {%4,%5,%6,%7}, {%8,%9}, {%0,%1,%2,%3};"
        : "+f"(c0), "+f"(c1), "+f"(c2), "+f"(c3)
        : "r"(a0), "r"(a1), "r"(a2), "r"(a3), "r"(b0), "r"(b1));
}

// ---------------- kernel ----------------
// Grid: (T_SEQ/M_TILE=16, B_BATCH=128). 256 threads = 8 warps.
// Warp layout: warpM = wid&1 (2 x 64 rows), warpN = wid>>1 (4 x 32 cols per chunk).
__global__ void __launch_bounds__(256, 1)
C2Q_15032385536516_kernel(const float* __restrict__ U,
                          const float* __restrict__ S,
                          float* __restrict__ Out)
{
    extern __shared__ char smem[];
    uint32_t* As = reinterpret_cast<uint32_t*>(smem);      // [128][A_STRIDE] tf32 probs
    const uint32_t sbase = smem_u32(smem);

    const int tid  = threadIdx.x;
    const int lane = tid & 31;
    const int wid  = tid >> 5;
    const int b    = blockIdx.y;
    const int m0   = blockIdx.x * M_TILE;
    const float* __restrict__ Ub = U + (size_t)b * K_DIM * N_DIM;

    // ---- prologue: async-load B chunk 0 into buffer 0 ----
    {
        const uint32_t bb = sbase + A_BYTES;
#pragma unroll
        for (int it = 0; it < 16; ++it) {
            const int idx = it * 256 + tid;
            const int k   = idx >> 5;          // 0..127
            const int n4  = idx & 31;          // float4 index within row
            cp_async16(bb + (uint32_t)(k * B_STRIDE + n4 * 4) * 4u,
                       Ub + (size_t)k * N_DIM + n4 * 4);
        }
        cp_commit();
    }

    // ---- fused softmax: 2 threads per row, each owns 64 of 128 cols ----
    {
        const int row  = tid >> 1;
        const int half = tid & 1;
        const float4* sp = reinterpret_cast<const float4*>(
            S + (size_t)(b * T_SEQ + m0 + row) * K_DIM + half * 64);
        float4 e[16];
        float sum = 0.f;
#pragma unroll
        for (int i = 0; i < 16; ++i) {
            float4 x = sp[i];
            e[i].x = __expf(x.x); e[i].y = __expf(x.y);
            e[i].z = __expf(x.z); e[i].w = __expf(x.w);
            sum += (e[i].x + e[i].y) + (e[i].z + e[i].w);
        }
        sum += __shfl_xor_sync(0xffffffffu, sum, 1);
        const float inv = 1.0f / sum;
        uint32_t* arow = As + row * A_STRIDE + half * 64;
#pragma unroll
        for (int i = 0; i < 16; ++i) {
            arow[4 * i + 0] = f32_to_tf32(e[i].x * inv);
            arow[4 * i + 1] = f32_to_tf32(e[i].y * inv);
            arow[4 * i + 2] = f32_to_tf32(e[i].z * inv);
            arow[4 * i + 3] = f32_to_tf32(e[i].w * inv);
        }
    }

    // ---- per-thread fragment bases ----
    const int warpM = wid & 1;
    const int warpN = wid >> 1;
    // ldmatrix A: lane -> (tile = lane>>3, row-in-tile = lane&7)
    //   tiles 0/1 : rows m+0..7 / m+8..15 at k-bytes +0
    //   tiles 2/3 : same rows at k-bytes +16
    const int l8 = lane & 7;
    const int tl = lane >> 3;
    uint32_t aLdsm[4];
#pragma unroll
    for (int mf = 0; mf < 4; ++mf) {
        const int row = warpM * 64 + mf * 16 + ((tl & 1) << 3) + l8;
        aLdsm[mf] = sbase + (uint32_t)(row * A_STRIDE) * 4u + (uint32_t)(tl >> 1) * 16u;
    }
    const int bIdx0 = (lane & 3) * B_STRIDE + warpN * 32 + (lane >> 2);
    float* outBase = Out + (size_t)(b * T_SEQ + m0) * N_DIM;

    // ---- main loop over 4 N-chunks, double-buffered B ----
#pragma unroll 1
    for (int c = 0; c < NCHUNKS; ++c) {
        __syncthreads();   // all warps done with MMA on buffer (c+1)&1 (chunk c-1)

        if (c + 1 < NCHUNKS) {
            const uint32_t bb = sbase + A_BYTES + (uint32_t)((c + 1) & 1) * B_BYTES;
            const int n0 = (c + 1) * NCHUNK;
#pragma unroll
            for (int it = 0; it < 16; ++it) {
                const int idx = it * 256 + tid;
                const int k   = idx >> 5;
                const int n4  = idx & 31;
                cp_async16(bb + (uint32_t)(k * B_STRIDE + n4 * 4) * 4u,
                           Ub + (size_t)k * N_DIM + n0 + n4 * 4);
            }
            cp_commit();
            cp_wait<1>();   // chunk c complete (one group pending)
        } else {
            cp_wait<0>();   // last chunk: everything complete
        }
        __syncthreads();    // chunk c data visible to all warps

        const uint32_t* Bp = reinterpret_cast<const uint32_t*>(
            smem + A_BYTES + (size_t)(c & 1) * B_BYTES);

        float acc[4][4][4];
#pragma unroll
        for (int mf = 0; mf < 4; ++mf)
#pragma unroll
            for (int nf = 0; nf < 4; ++nf)
#pragma unroll
                for (int r = 0; r < 4; ++r) acc[mf][nf][r] = 0.f;

        // ---- software-pipelined K loop: prefetch s+1 frags during MMA of s ----
        uint32_t a[2][4][4];
        uint32_t bf[2][4][2];

        // prefetch s = 0
#pragma unroll
        for (int mf = 0; mf < 4; ++mf)
            ldsm_x4(a[0][mf][0], a[0][mf][1], a[0][mf][2], a[0][mf][3], aLdsm[mf]);
#pragma unroll
        for (int nf = 0; nf < 4; ++nf) {
            const int base = bIdx0 + nf * 8;
            bf[0][nf][0] = Bp[base];
            bf[0][nf][1] = Bp[base + 4 * B_STRIDE];
        }

#pragma unroll
        for (int s = 0; s < 16; ++s) {
            const int cur = s & 1;
            const int nxt = cur ^ 1;
            if (s < 15) {
#pragma unroll
                for (int mf = 0; mf < 4; ++mf)
                    ldsm_x4(a[nxt][mf][0], a[nxt][mf][1], a[nxt][mf][2], a[nxt][mf][3],
                            aLdsm[mf] + (uint32_t)(s + 1) * 32u);
#pragma unroll
                for (int nf = 0; nf < 4; ++nf) {
                    const int base = bIdx0 + (s + 1) * 8 * B_STRIDE + nf * 8;
                    bf[nxt][nf][0] = Bp[base];
                    bf[nxt][nf][1] = Bp[base + 4 * B_STRIDE];
                }
            }
#pragma unroll
            for (int mf = 0; mf < 4; ++mf)
#pragma unroll
                for (int nf = 0; nf < 4; ++nf)
                    mma_tf32(acc[mf][nf][0], acc[mf][nf][1],
                             acc[mf][nf][2], acc[mf][nf][3],
                             a[cur][mf][0], a[cur][mf][1], a[cur][mf][2], a[cur][mf][3],
                             bf[cur][nf][0], bf[cur][nf][1]);
        }

        // ---- epilogue: stream accumulators to GMEM ----
        const int colBase = c * NCHUNK + warpN * 32 + 2 * (lane & 3);
        const int rowBase = warpM * 64 + (lane >> 2);
#pragma unroll
        for (int mf = 0; mf < 4; ++mf) {
            const int r0 = rowBase + mf * 16;
#pragma unroll
            for (int nf = 0; nf < 4; ++nf) {
                const int col = colBase + nf * 8;
                float2 v0 = make_float2(acc[mf][nf][0], acc[mf][nf][1]);
                float2 v1 = make_float2(acc[mf][nf][2], acc[mf][nf][3]);
                __stcs(reinterpret_cast<float2*>(outBase + (size_t)r0 * N_DIM + col), v0);
                __stcs(reinterpret_cast<float2*>(outBase + (size_t)(r0 + 8) * N_DIM + col), v1);
            }
        }
    }
}

extern "C" void kernel_launch(void* const* d_in, const int* in_sizes, int n_in,
                              void* d_out, int out_size)
{
    const float* U = (const float*)d_in[0];
    const float* S = (const float*)d_in[1];
    // Robustness: U has 8.4M elements, S has 33.5M. Swap if order differs.
    if (n_in >= 2 && in_sizes[0] == B_BATCH * T_SEQ * K_DIM) {
        const float* t = U; U = S; S = t;
    }
    float* Out = (float*)d_out;

    static int attr_set = 0;
    if (!attr_set) {
        cudaFuncSetAttribute(C2Q_15032385536516_kernel,
                             cudaFuncAttributeMaxDynamicSharedMemorySize, SMEM_TOTAL);
        attr_set = 1;
    }
    dim3 grid(T_SEQ / M_TILE, B_BATCH, 1);  // (16, 128)
    C2Q_15032385536516_kernel<<<grid, 256, SMEM_TOTAL>>>(U, S, Out);
}